// round 1
// baseline (speedup 1.0000x reference)
#include <cuda_runtime.h>
#include <math.h>

// Problem shape (fixed by the dataset): T=4, B=32, N=1024, C=256
#define C_DIM    256
#define T_STEPS  4
#define TILE_M   64
#define KC       32
#define THREADS  256
#define NBLK     2048            // 131072 / TILE_M
#define TOTAL_EL 33554432        // T*B*N*C

// Scratch (allocation-free rule: __device__ globals)
__device__ float g_mid[TOTAL_EL];                 // pre-BN projection output [M, C]
__device__ float g_partial[2 * C_DIM * NBLK];     // per-CTA channel sums / sumsq
__device__ float g_scale[C_DIM];                  // gamma * rstd
__device__ float g_shift[C_DIM];                  // beta - mean * gamma * rstd

__device__ __forceinline__ float sigmoidf_(float x) {
    return 1.0f / (1.0f + expf(-x));
}

// One 64x256 = sXT[ C ][ TILE_M ] @ W^T tile-GEMM. W streamed through sW in
// 32-k chunks. Each thread owns an 8x8 micro-tile: rows m0..m0+7, cols d0..d0+7.
// The leading __syncthreads() of each chunk also orders any smem writes the
// caller did just before invoking (tile staging / fused transpose).
__device__ __forceinline__ void gemm_tile(const float* __restrict__ sXT,
                                          float* __restrict__ sW,
                                          const float* __restrict__ Wg,
                                          float acc[64], int tid)
{
    const int mg = tid >> 5, dg = tid & 31;
    const int m0 = mg << 3, d0 = dg << 3;
    const int lw  = tid & 7;     // which 4-k group this thread loads
    const int dwb = tid >> 3;    // base output-row of W this thread loads

    for (int kc = 0; kc < C_DIM; kc += KC) {
        __syncthreads();
        // Stage W[d][kc..kc+31] transposed into sW[kk][d]
        #pragma unroll
        for (int it = 0; it < 8; it++) {
            int d = dwb + (it << 5);
            float4 w4 = *(const float4*)(Wg + d * C_DIM + kc + (lw << 2));
            int kk = lw << 2;
            sW[(kk + 0) * C_DIM + d] = w4.x;
            sW[(kk + 1) * C_DIM + d] = w4.y;
            sW[(kk + 2) * C_DIM + d] = w4.z;
            sW[(kk + 3) * C_DIM + d] = w4.w;
        }
        __syncthreads();
        #pragma unroll 4
        for (int kk = 0; kk < KC; kk++) {
            float a[8], w[8];
            const float* ap = sXT + (kc + kk) * TILE_M + m0;
            *(float4*)(a)     = *(const float4*)(ap);
            *(float4*)(a + 4) = *(const float4*)(ap + 4);
            const float* wp = sW + kk * C_DIM + d0;
            *(float4*)(w)     = *(const float4*)(wp);
            *(float4*)(w + 4) = *(const float4*)(wp + 4);
            #pragma unroll
            for (int i = 0; i < 8; i++)
                #pragma unroll
                for (int j = 0; j < 8; j++)
                    acc[i * 8 + j] = fmaf(a[i], w[j], acc[i * 8 + j]);
        }
    }
}

__global__ void __launch_bounds__(THREADS, 1)
fused_gemm_kernel(const float* __restrict__ xa, const float* __restrict__ xl,
                  const float* __restrict__ Watt, const float* __restrict__ batt,
                  const float* __restrict__ Wlsm, const float* __restrict__ blsm,
                  const float* __restrict__ Wproj, const float* __restrict__ bproj)
{
    extern __shared__ float sm[];
    float* sAT = sm;                                   // [C][TILE_M]  64 KB
    float* sLT = sm + C_DIM * TILE_M;                  // [C][TILE_M]  64 KB
    float* sG  = sm + 2 * C_DIM * TILE_M;              // [TILE_M][C]  64 KB
    float* sW  = sm + 3 * C_DIM * TILE_M;              // [KC][C]      32 KB

    const int tid = threadIdx.x;
    const size_t row0 = (size_t)blockIdx.x * TILE_M;
    const int mg = tid >> 5, dg = tid & 31;
    const int m0 = mg << 3, d0 = dg << 3;

    // ---- Stage A and L tiles transposed: sXT[c][m] ----
    {
        const float4* A4 = (const float4*)(xa + row0 * C_DIM);
        const float4* L4 = (const float4*)(xl + row0 * C_DIM);
        #pragma unroll
        for (int i = 0; i < 16; i++) {
            int idx = tid + (i << 8);          // 0..4095 over 64 rows x 64 float4
            int r = idx >> 6, c4 = idx & 63;
            float4 va = A4[idx];
            float4 vl = L4[idx];
            int cb = c4 << 2;
            sAT[(cb + 0) * TILE_M + r] = va.x;
            sAT[(cb + 1) * TILE_M + r] = va.y;
            sAT[(cb + 2) * TILE_M + r] = va.z;
            sAT[(cb + 3) * TILE_M + r] = va.w;
            sLT[(cb + 0) * TILE_M + r] = vl.x;
            sLT[(cb + 1) * TILE_M + r] = vl.y;
            sLT[(cb + 2) * TILE_M + r] = vl.z;
            sLT[(cb + 3) * TILE_M + r] = vl.w;
        }
    }
    // (gemm_tile's first __syncthreads orders the staging writes)

    float acc[64];

    // ---- PASS 1: gate_lsm = sigmoid(a . Watt^T + batt)  -> sG[m][c] ----
    #pragma unroll
    for (int q = 0; q < 64; q++) acc[q] = 0.0f;
    gemm_tile(sAT, sW, Watt, acc, tid);
    #pragma unroll
    for (int j = 0; j < 8; j++) {
        float b = batt[d0 + j];
        #pragma unroll
        for (int i = 0; i < 8; i++)
            sG[(m0 + i) * C_DIM + d0 + j] = sigmoidf_(acc[i * 8 + j] + b);
    }

    // ---- PASS 2: gate_attn = sigmoid(l . Wlsm^T + blsm);
    //      fused = a*gate_attn + l*gate_lsm (in-place into acc) ----
    #pragma unroll
    for (int q = 0; q < 64; q++) acc[q] = 0.0f;
    gemm_tile(sLT, sW, Wlsm, acc, tid);
    #pragma unroll
    for (int j = 0; j < 8; j++) {
        float b = blsm[d0 + j];
        int c = d0 + j;
        #pragma unroll
        for (int i = 0; i < 8; i++) {
            int m = m0 + i;
            float ga = sigmoidf_(acc[i * 8 + j] + b);
            float av = sAT[c * TILE_M + m];
            float lv = sLT[c * TILE_M + m];
            acc[i * 8 + j] = av * ga + lv * sG[m * C_DIM + c];
        }
    }
    __syncthreads();
    // write fused transposed over sAT (each thread owns exactly its (m,c) block)
    #pragma unroll
    for (int j = 0; j < 8; j++)
        #pragma unroll
        for (int i = 0; i < 8; i++)
            sAT[(d0 + j) * TILE_M + (m0 + i)] = acc[i * 8 + j];

    // ---- PASS 3: out = fused . Wproj^T + bproj ----
    {
        float fz[64];
        #pragma unroll
        for (int q = 0; q < 64; q++) fz[q] = acc[q];   // keep regs alive cheaply
        (void)fz;
    }
    #pragma unroll
    for (int q = 0; q < 64; q++) acc[q] = 0.0f;
    gemm_tile(sAT, sW, Wproj, acc, tid);

    float cs[8], cs2[8];
    #pragma unroll
    for (int j = 0; j < 8; j++) { cs[j] = 0.0f; cs2[j] = 0.0f; }
    #pragma unroll
    for (int i = 0; i < 8; i++) {
        float o[8];
        #pragma unroll
        for (int j = 0; j < 8; j++) {
            o[j] = acc[i * 8 + j] + bproj[d0 + j];
            cs[j]  += o[j];
            cs2[j] = fmaf(o[j], o[j], cs2[j]);
        }
        float4* dst = (float4*)&g_mid[(row0 + m0 + i) * C_DIM + d0];
        dst[0] = make_float4(o[0], o[1], o[2], o[3]);
        dst[1] = make_float4(o[4], o[5], o[6], o[7]);
    }

    // ---- deterministic per-channel partial reduction (reuse sG) ----
    float* sRed = sG;  // need 256*8*2 = 4096 floats
    #pragma unroll
    for (int j = 0; j < 8; j++) {
        sRed[(d0 + j) * 8 + mg]        = cs[j];
        sRed[2048 + (d0 + j) * 8 + mg] = cs2[j];
    }
    __syncthreads();
    {
        int d = tid;
        float s = 0.0f, s2 = 0.0f;
        #pragma unroll
        for (int g = 0; g < 8; g++) {
            s  += sRed[d * 8 + g];
            s2 += sRed[2048 + d * 8 + g];
        }
        g_partial[(size_t)d * NBLK + blockIdx.x] = s;
        g_partial[(size_t)C_DIM * NBLK + (size_t)d * NBLK + blockIdx.x] = s2;
    }
}

__global__ void bn_stats_kernel(const float* __restrict__ gamma,
                                const float* __restrict__ beta, int Mtot)
{
    __shared__ double sh0[256];
    __shared__ double sh1[256];
    int d = blockIdx.x, t = threadIdx.x;
    const float* ps = g_partial + (size_t)d * NBLK;
    const float* pq = g_partial + (size_t)C_DIM * NBLK + (size_t)d * NBLK;
    double s = 0.0, s2 = 0.0;
    for (int i = t; i < NBLK; i += 256) { s += ps[i]; s2 += pq[i]; }
    sh0[t] = s; sh1[t] = s2;
    __syncthreads();
    for (int off = 128; off > 0; off >>= 1) {
        if (t < off) { sh0[t] += sh0[t + off]; sh1[t] += sh1[t + off]; }
        __syncthreads();
    }
    if (t == 0) {
        double inv  = 1.0 / (double)Mtot;
        double mean = sh0[0] * inv;
        double var  = sh1[0] * inv - mean * mean;
        float rstd = (float)(1.0 / sqrt(var + 1e-5));
        float gm = gamma[d];
        g_scale[d] = gm * rstd;
        g_shift[d] = beta[d] - (float)mean * gm * rstd;
    }
}

__global__ void lif_kernel(const float* __restrict__ lifw,
                           float* __restrict__ out, int BNC)
{
    int i = (blockIdx.x * blockDim.x + threadIdx.x) << 2;
    if (i >= BNC) return;
    float ti = 1.0f / (1.0f + expf(-lifw[0]));   // sigmoid(lif_w)
    int c = i & (C_DIM - 1);
    float4 sc = *(const float4*)&g_scale[c];
    float4 sf = *(const float4*)&g_shift[c];
    float v0 = 0.f, v1 = 0.f, v2 = 0.f, v3 = 0.f;
    #pragma unroll
    for (int t = 0; t < T_STEPS; t++) {
        float4 x = *(const float4*)&g_mid[(size_t)t * BNC + i];
        float y0 = fmaf(x.x, sc.x, sf.x);
        float y1 = fmaf(x.y, sc.y, sf.y);
        float y2 = fmaf(x.z, sc.z, sf.z);
        float y3 = fmaf(x.w, sc.w, sf.w);
        v0 += (y0 - v0) * ti;
        v1 += (y1 - v1) * ti;
        v2 += (y2 - v2) * ti;
        v3 += (y3 - v3) * ti;
        float s0 = (v0 >= 1.0f) ? 1.0f : 0.0f;
        float s1 = (v1 >= 1.0f) ? 1.0f : 0.0f;
        float s2 = (v2 >= 1.0f) ? 1.0f : 0.0f;
        float s3 = (v3 >= 1.0f) ? 1.0f : 0.0f;
        v0 = (s0 > 0.f) ? 0.f : v0;
        v1 = (s1 > 0.f) ? 0.f : v1;
        v2 = (s2 > 0.f) ? 0.f : v2;
        v3 = (s3 > 0.f) ? 0.f : v3;
        *(float4*)&out[(size_t)t * BNC + i] = make_float4(s0, s1, s2, s3);
    }
}

extern "C" void kernel_launch(void* const* d_in, const int* in_sizes, int n_in,
                              void* d_out, int out_size)
{
    const float* xa    = (const float*)d_in[0];   // x_attn [T,B,N,C]
    const float* xl    = (const float*)d_in[1];   // x_lsm
    const float* Watt  = (const float*)d_in[2];
    const float* batt  = (const float*)d_in[3];
    const float* Wlsm  = (const float*)d_in[4];
    const float* blsm  = (const float*)d_in[5];
    const float* Wproj = (const float*)d_in[6];
    const float* bproj = (const float*)d_in[7];
    const float* gamma = (const float*)d_in[8];
    const float* beta  = (const float*)d_in[9];
    const float* lifw  = (const float*)d_in[10];

    int total = in_sizes[0];        // 33554432
    int M     = total / C_DIM;      // 131072
    int nblk  = M / TILE_M;         // 2048
    int BNC   = total / T_STEPS;    // 8388608

    size_t smem = (size_t)(3 * C_DIM * TILE_M + KC * C_DIM) * sizeof(float); // 224 KB
    cudaFuncSetAttribute(fused_gemm_kernel,
                         cudaFuncAttributeMaxDynamicSharedMemorySize, (int)smem);

    fused_gemm_kernel<<<nblk, THREADS, smem>>>(xa, xl, Watt, batt, Wlsm, blsm,
                                               Wproj, bproj);
    bn_stats_kernel<<<C_DIM, 256>>>(gamma, beta, M);
    lif_kernel<<<(BNC / 4 + 255) / 256, 256>>>(lifw, (float*)d_out, BNC);
}